// round 9
// baseline (speedup 1.0000x reference)
#include <cuda_runtime.h>
#include <cooperative_groups.h>
#include <math.h>

namespace cg = cooperative_groups;

// Problem constants
#define NB      32          // batch N
#define D_IN    513         // S+1
#define TOTAL   262917      // per-(t,n) output row length
#define P_OFF   260
#define M_OFF   261
#define MN_OFF  262405
#define M_PER_N 262144      // S * ND * H

// Scratch (device globals — no allocation allowed)
__device__ float g_M [NB * M_PER_N];   // [n][s*512 + d*256 + h]
__device__ float g_Mn[NB * 512];       // [n][d*256 + h]
__device__ float g_loc[NB];
__device__ float g_v  [NB];
__device__ int   g_nonzero = 0;        // sticky: set iff rnn input has any nonzero

// ---------------- f32x2 helper (tied accumulator: no result MOVs) ----------------
__device__ __forceinline__ void ffma2(unsigned long long& acc,
                                      unsigned long long a, unsigned long long b) {
    asm("fma.rn.f32x2 %0, %1, %2, %0;" : "+l"(acc) : "l"(a), "l"(b));
}
union F2U { unsigned long long u; float2 f; };

// ---------------- mbarrier helpers (primitives proven in R6) ----------------
__device__ __forceinline__ void mbar_init(unsigned addr, unsigned count) {
    asm volatile("mbarrier.init.shared.b64 [%0], %1;" :: "r"(addr), "r"(count) : "memory");
}
__device__ __forceinline__ void mbar_wait_cluster(unsigned addr, unsigned parity) {
    asm volatile(
        "{\n\t.reg .pred P1;\n\t"
        "LAB_%=:\n\t"
        "mbarrier.try_wait.parity.acquire.cluster.shared::cta.b64 P1, [%0], %1, 0x989680;\n\t"
        "@P1 bra DONE_%=;\n\t"
        "bra LAB_%=;\n\t"
        "DONE_%=:\n\t}"
        :: "r"(addr), "r"(parity) : "memory");
}
__device__ __forceinline__ void arrive_remote(unsigned lmbar, unsigned rank) {
    asm volatile(
        "{\n\t.reg .b32 rm;\n\t"
        "mapa.shared::cluster.u32 rm, %0, %1;\n\t"
        "mbarrier.arrive.release.cluster.shared::cluster.b64 _, [rm];\n\t}"
        :: "r"(lmbar), "r"(rank) : "memory");
}

// ---------------- flag kernel (sticky, no reset needed) ----------------
__global__ void scan_flag_kernel(const float* __restrict__ rnn) {
    if (g_nonzero != 0) return;   // sticky early-out (deterministic final value)
    const int NV4 = (NB * TOTAL) / 4;   // exact
    const float4* p = reinterpret_cast<const float4*>(rnn);
    bool nz = false;
    for (int i = blockIdx.x * blockDim.x + threadIdx.x; i < NV4; i += gridDim.x * blockDim.x) {
        float4 v = p[i];
        nz |= (v.x != 0.f) | (v.y != 0.f) | (v.z != 0.f) | (v.w != 0.f);
    }
    if (__syncthreads_or(nz) && threadIdx.x == 0) atomicOr(&g_nonzero, 1);
}

// ---------------- GRU cluster kernel ----------------
// grid (8, 8, 2): x = cluster rank (32-col slice of h), y = n-group (4 n), z = direction.
// Per step: matvec (W in regs, f32x2), butterfly, Gx exchange, gates -> hbuf[p],
// bar, 1 thread does 8 remote mbarrier arrives, pull threads wait locally + pull,
// bar. Double-buffered hbuf + 2 parity mbarriers give safe 1-step pipelining.
struct __align__(16) GruSmem {
    float Hw[4][4][68];      // [nn][q][64 + 4 pad]  full h for the 4 batch rows
    float hbuf[2][4][32];    // [parity][nn][i]  own 32-col slice of h_new
    float xs[4][512];        // input sequence per batch row
    float Gx[128][4];        // gate exchange: rows {pr,pz,ghn,gin} x [nn]
    unsigned long long mbar[2];
};

__global__ void __cluster_dims__(8, 1, 1) __launch_bounds__(384, 1)
gru_kernel(const float* __restrict__ inputs,
           const float* __restrict__ w_ih, const float* __restrict__ w_hh,
           const float* __restrict__ b_ih, const float* __restrict__ b_hh)
{
    __shared__ GruSmem sm;

    const int tid = threadIdx.x;
    const int bc  = blockIdx.x;       // cluster rank / column slice
    const int gN  = blockIdx.y;
    const int dd  = blockIdx.z;
    const int rr  = tid >> 2;
    const int q   = tid & 3;
    const int rowG = dd * 768 + ((rr >> 5) << 8) + (bc << 5) + (rr & 31);

    cg::cluster_group cluster = cg::this_cluster();

    // ---- W_hh slice into registers (64 floats = 32 f32x2) ----
    unsigned long long w2[32];
    {
        const ulonglong2* wg = reinterpret_cast<const ulonglong2*>(w_hh + (size_t)rowG * 256 + q * 64);
#pragma unroll
        for (int i = 0; i < 16; ++i) { ulonglong2 t = wg[i]; w2[2 * i] = t.x; w2[2 * i + 1] = t.y; }
    }
    const float wihr = w_ih[rowG];
    const float bihr = b_ih[rowG];
    const float bhhr = b_hh[rowG];

    // inputs: xs[nn][s] = inputs[0][n][s]
    for (int idx = tid; idx < 4 * 512; idx += 384) {
        int nn = idx >> 9, s = idx & 511;
        sm.xs[nn][s] = inputs[(gN * 4 + nn) * D_IN + s];
    }
    // h0 = 0
    for (int idx = tid; idx < 4 * 4 * 68; idx += 384)
        (&sm.Hw[0][0][0])[idx] = 0.f;

    const unsigned mb0 = (unsigned)__cvta_generic_to_shared(&sm.mbar[0]);
    const unsigned mb1 = (unsigned)__cvta_generic_to_shared(&sm.mbar[1]);
    if (tid == 0) { mbar_init(mb0, 8); mbar_init(mb1, 8); }
    __syncthreads();
    cluster.sync();   // mbars init'd cluster-wide + h0 ready before any step

    const int bcq = bc >> 1;               // quarter index of own slice within Hw
    const int bco = (bc & 1) * 32;         // float offset within that quarter

    for (int t = 0; t < 512; ++t) {
        const int p = t & 1;
        const int s = dd ? (511 - t) : t;

        // ---- matvec: gh partial over this thread's k-quarter, all 4 batch rows ----
        float part[4];
#pragma unroll
        for (int nn = 0; nn < 4; ++nn) {
            const ulonglong2* hq = reinterpret_cast<const ulonglong2*>(&sm.Hw[nn][q][0]);
            unsigned long long a0 = 0ull, a1 = 0ull;
#pragma unroll
            for (int kk = 0; kk < 16; ++kk) {
                ulonglong2 hv = hq[kk];
                ffma2(a0, w2[2 * kk],     hv.x);
                ffma2(a1, w2[2 * kk + 1], hv.y);
            }
            F2U u0, u1; u0.u = a0; u1.u = a1;
            part[nn] = (u0.f.x + u0.f.y) + (u1.f.x + u1.f.y);
        }

        // ---- butterfly: reduce over q, redistribute nn -> lane q ----
        const int qb = q & 1, qc = q >> 1;
        float keep_lo = qb ? part[1] : part[0];
        float send_lo = qb ? part[0] : part[1];
        float keep_hi = qb ? part[3] : part[2];
        float send_hi = qb ? part[2] : part[3];
        float s0 = keep_lo + __shfl_xor_sync(0xffffffffu, send_lo, 1);
        float s1 = keep_hi + __shfl_xor_sync(0xffffffffu, send_hi, 1);
        float mine = qc ? s1 : s0;
        float othr = qc ? s0 : s1;
        float gh = mine + __shfl_xor_sync(0xffffffffu, othr, 2) + bhhr;  // full gh for nn=q
        float gi = fmaf(sm.xs[q][s], wihr, bihr);

        if (rr < 64) sm.Gx[rr][q] = gh + gi;
        else { sm.Gx[rr][q] = gh; sm.Gx[rr + 32][q] = gi; }
        __syncthreads();

        // ---- gates (warps 0..3 = 4 n x 32 cols), write own slice to hbuf ----
        float hnew = 0.f;
        if (tid < 128) {
            const int n2 = tid >> 5;
            const int i  = tid & 31;
            float pr  = sm.Gx[i][n2];
            float pz  = sm.Gx[32 + i][n2];
            float ghn = sm.Gx[64 + i][n2];
            float gin = sm.Gx[96 + i][n2];
            float r = 1.f / (1.f + __expf(-pr));
            float z = 1.f / (1.f + __expf(-pz));
            float npre = fmaf(r, ghn, gin);
            float tn = 1.f - 2.f / (1.f + __expf(2.f * npre));
            float hold = sm.Hw[n2][bcq][bco + i];
            hnew = fmaf(z, hold - tn, tn);   // (1-z)*tn + z*hold
            sm.hbuf[p][n2][i] = hnew;
        }
        __syncthreads();   // hbuf[p] complete CTA-wide

        // ---- global store off the handshake critical path ----
        if (tid < 128) {
            const int n2 = tid >> 5;
            const int i  = tid & 31;
            const int n = gN * 4 + n2;
            const int colg = (bc << 5) + i;
            g_M[(size_t)n * M_PER_N + s * 512 + dd * 256 + colg] = hnew;
            if (t == 511)
                g_Mn[n * 512 + dd * 256 + colg] = hnew;
        }

        if (t < 511) {
            // signal: my hbuf[p] is ready -> arrive on every CTA's mbar[p]
            if (tid == 0) {
#pragma unroll
                for (int dst = 0; dst < 8; ++dst)
                    arrive_remote(p ? mb1 : mb0, (unsigned)dst);
            }
            // consume: wait for all 8 slices, then pull into Hw
            if (tid < 256) {
                mbar_wait_cluster(p ? mb1 : mb0, (unsigned)((t >> 1) & 1));
                const int src = tid >> 5;
                const int rem = tid & 31;
                const int nn  = rem >> 3;
                const int i4  = rem & 7;
                const float* peer = cluster.map_shared_rank(&sm.hbuf[p][0][0], (unsigned)src);
                float4 v = reinterpret_cast<const float4*>(peer)[nn * 8 + i4];
                *reinterpret_cast<float4*>(&sm.Hw[nn][src >> 1][(src & 1) * 32 + i4 * 4]) = v;
            }
            __syncthreads();
        }
    }
    cluster.sync();   // no CTA exits while a peer may still read its hbuf
}

// ---------------- MLP kernel: grid (NB, 2) — y: 0=actor, 1=critic ----------------
__device__ __forceinline__ void layer4(const float* __restrict__ W, const float* __restrict__ B,
                                       const float* __restrict__ in, float* out, int indim)
{
    const int warp = threadIdx.x >> 5, lane = threadIdx.x & 31;
    const int nk4 = indim >> 2;
    const float4* in4 = reinterpret_cast<const float4*>(in);
    for (int j0 = warp * 32; j0 < warp * 32 + 32; j0 += 4) {
        const float4* w0 = reinterpret_cast<const float4*>(W + (size_t)j0 * indim);
        const float4* w1 = reinterpret_cast<const float4*>(W + (size_t)(j0 + 1) * indim);
        const float4* w2 = reinterpret_cast<const float4*>(W + (size_t)(j0 + 2) * indim);
        const float4* w3 = reinterpret_cast<const float4*>(W + (size_t)(j0 + 3) * indim);
        float a0 = 0.f, a1 = 0.f, a2 = 0.f, a3 = 0.f;
        for (int k = lane; k < nk4; k += 32) {
            float4 x = in4[k];
            float4 v0 = __ldg(w0 + k);
            float4 v1 = __ldg(w1 + k);
            float4 v2 = __ldg(w2 + k);
            float4 v3 = __ldg(w3 + k);
            a0 += v0.x * x.x + v0.y * x.y + v0.z * x.z + v0.w * x.w;
            a1 += v1.x * x.x + v1.y * x.y + v1.z * x.z + v1.w * x.w;
            a2 += v2.x * x.x + v2.y * x.y + v2.z * x.z + v2.w * x.w;
            a3 += v3.x * x.x + v3.y * x.y + v3.z * x.z + v3.w * x.w;
        }
#pragma unroll
        for (int o = 16; o; o >>= 1) {
            a0 += __shfl_down_sync(0xffffffffu, a0, o);
            a1 += __shfl_down_sync(0xffffffffu, a1, o);
            a2 += __shfl_down_sync(0xffffffffu, a2, o);
            a3 += __shfl_down_sync(0xffffffffu, a3, o);
        }
        if (lane == 0) {
            out[j0]     = fmaxf(a0 + B[j0],     0.f);
            out[j0 + 1] = fmaxf(a1 + B[j0 + 1], 0.f);
            out[j0 + 2] = fmaxf(a2 + B[j0 + 2], 0.f);
            out[j0 + 3] = fmaxf(a3 + B[j0 + 3], 0.f);
        }
    }
}

__global__ void __launch_bounds__(256)
mlp_kernel(const float* __restrict__ rnn,
           const float* __restrict__ aw0, const float* __restrict__ ab0,
           const float* __restrict__ aw1, const float* __restrict__ ab1,
           const float* __restrict__ alw, const float* __restrict__ alb,
           const float* __restrict__ cw0, const float* __restrict__ cb0,
           const float* __restrict__ cw1, const float* __restrict__ cb1,
           const float* __restrict__ cow, const float* __restrict__ cob)
{
    __shared__ __align__(16) float hn[1024];
    __shared__ __align__(16) float h1[256];
    __shared__ __align__(16) float h2[256];
    const int n = blockIdx.x, br = blockIdx.y, tid = threadIdx.x;
    const bool newep = (g_nonzero == 0);
    const float* hx = rnn + (size_t)n * TOTAL;
    int P = (int)hx[P_OFF];
    if (P < 0) P = 0; if (P > 511) P = 511;

    const float* w0 = br ? cw0 : aw0;  const float* b0 = br ? cb0 : ab0;
    const float* w1 = br ? cw1 : aw1;  const float* b1 = br ? cb1 : ab1;
    const float* wo = br ? cow : alw;  const float* bo = br ? cob : alb;

    // hn = [ Mn interleaved (h*2 + d), r = M[P][n][:] ]
    for (int k = tid; k < 1024; k += 256) {
        float v;
        if (k < 512) {
            int h = k >> 1, d2 = k & 1;
            v = newep ? g_Mn[n * 512 + d2 * 256 + h] : hx[MN_OFF + d2 * 256 + h];
        } else {
            int kk = k - 512;
            v = newep ? g_M[(size_t)n * M_PER_N + P * 512 + kk] : hx[M_OFF + P * 512 + kk];
        }
        hn[k] = v;
    }
    __syncthreads();

    layer4(w0, b0, hn, h1, 1024);
    __syncthreads();
    layer4(w1, b1, h1, h2, 256);
    __syncthreads();
    if (tid < 32) {
        float acc = 0.f;
        for (int k = tid; k < 256; k += 32) acc = fmaf(wo[k], h2[k], acc);
#pragma unroll
        for (int o = 16; o; o >>= 1) acc += __shfl_down_sync(0xffffffffu, acc, o);
        if (tid == 0) { if (br) g_v[n] = acc + bo[0]; else g_loc[n] = acc + bo[0]; }
    }
}

// ---------------- output fill kernel ----------------
// out is 9 t-slices of (NB, TOTAL): t=0..7 = hx_out, t=8 = hx_out[-1] (== t=7)
__global__ void __launch_bounds__(256)
fill_kernel(const float* __restrict__ inputs, const float* __restrict__ rnn,
            const float* __restrict__ eps, const float* __restrict__ logstd,
            float* __restrict__ out)
{
    int o = blockIdx.x * 256 + threadIdx.x;
    if (o >= TOTAL) return;
    const int t9 = blockIdx.y;
    const int n  = blockIdx.z;
    const int teff = (t9 < 8) ? t9 : 7;
    const float* hx = rnn + (size_t)n * TOTAL;
    const bool newep = (g_nonzero == 0);

    float val;
    if (o >= M_OFF) {
        if (o < MN_OFF) {
            int m = o - M_OFF;
            val = newep ? g_M[(size_t)n * M_PER_N + m] : hx[o];
        } else {
            val = newep ? g_Mn[n * 512 + (o - MN_OFF)] : hx[o];
        }
    } else if (o >= 4 && o < P_OFF) {
        val = hx[o];                         // hx_h passthrough
    } else if (o == P_OFF) {
        int P = (int)hx[P_OFF];
        val = (float)((P + 1) & 511);        // (P+1) % 512
    } else if (o == 0) {
        float act = inputs[(size_t)(teff * NB + n) * D_IN + (D_IN - 1)];
        float scale = expf(logstd[0]);
        val = (act < 0.f) ? fmaf(scale, eps[teff * NB + n], g_loc[n]) : act;
    } else if (o == 1) {
        val = g_loc[n];
    } else if (o == 2) {
        val = expf(logstd[0]);
    } else { // o == 3
        val = g_v[n];
    }
    __stcs(&out[(size_t)(t9 * NB + n) * TOTAL + o], val);
}

// ---------------- launch ----------------
extern "C" void kernel_launch(void* const* d_in, const int* in_sizes, int n_in,
                              void* d_out, int out_size)
{
    const float* inputs = (const float*)d_in[0];
    const float* rnn    = (const float*)d_in[1];
    const float* eps    = (const float*)d_in[2];
    const float* gwih   = (const float*)d_in[3];
    const float* gwhh   = (const float*)d_in[4];
    const float* gbih   = (const float*)d_in[5];
    const float* gbhh   = (const float*)d_in[6];
    const float* aw0    = (const float*)d_in[7];
    const float* ab0    = (const float*)d_in[8];
    const float* aw1    = (const float*)d_in[9];
    const float* ab1    = (const float*)d_in[10];
    const float* alw    = (const float*)d_in[11];
    const float* alb    = (const float*)d_in[12];
    const float* alogstd= (const float*)d_in[13];
    const float* cw0    = (const float*)d_in[14];
    const float* cb0    = (const float*)d_in[15];
    const float* cw1    = (const float*)d_in[16];
    const float* cb1    = (const float*)d_in[17];
    const float* cow    = (const float*)d_in[18];
    const float* cob    = (const float*)d_in[19];
    float* out = (float*)d_out;

    (void)in_sizes; (void)n_in; (void)out_size;

    scan_flag_kernel<<<512, 256>>>(rnn);
    gru_kernel<<<dim3(8, 8, 2), 384>>>(inputs, gwih, gwhh, gbih, gbhh);
    mlp_kernel<<<dim3(NB, 2), 256>>>(rnn, aw0, ab0, aw1, ab1, alw, alb,
                                     cw0, cb0, cw1, cb1, cow, cob);
    fill_kernel<<<dim3((TOTAL + 255) / 256, 9, NB), 256>>>(inputs, rnn, eps, alogstd, out);
}

// round 11
// speedup vs baseline: 1.5715x; 1.5715x over previous
#include <cuda_runtime.h>
#include <cooperative_groups.h>
#include <math.h>

namespace cg = cooperative_groups;

// Problem constants
#define NB      32          // batch N
#define D_IN    513         // S+1
#define TOTAL   262917      // per-(t,n) output row length
#define P_OFF   260
#define M_OFF   261
#define MN_OFF  262405
#define M_PER_N 262144      // S * ND * H
#define SLICE_F4 2103336    // NB*TOTAL/4 (exact)

// Scratch (device globals — no allocation allowed)
__device__ float g_M [NB * M_PER_N];   // [n][s*512 + d*256 + h]
__device__ float g_Mn[NB * 512];       // [n][d*256 + h]
__device__ float g_loc[NB];
__device__ float g_v  [NB];
__device__ int   g_nonzero = 0;        // sticky: set iff rnn input has any nonzero

// ---------------- f32x2 helper (tied accumulator: no result MOVs) ----------------
__device__ __forceinline__ void ffma2(unsigned long long& acc,
                                      unsigned long long a, unsigned long long b) {
    asm("fma.rn.f32x2 %0, %1, %2, %0;" : "+l"(acc) : "l"(a), "l"(b));
}
union F2U { unsigned long long u; float2 f; };

// ---------------- flag kernel (sticky, deterministic across replays) ----------------
__global__ void scan_flag_kernel(const float* __restrict__ rnn) {
    if (g_nonzero != 0) return;
    const int NV4 = (NB * TOTAL) / 4;
    const float4* p = reinterpret_cast<const float4*>(rnn);
    bool nz = false;
    for (int i = blockIdx.x * blockDim.x + threadIdx.x; i < NV4; i += gridDim.x * blockDim.x) {
        float4 v = p[i];
        nz |= (v.x != 0.f) | (v.y != 0.f) | (v.z != 0.f) | (v.w != 0.f);
    }
    if (__syncthreads_or(nz) && threadIdx.x == 0) atomicOr(&g_nonzero, 1);
}

// ---------------- GRU cluster kernel (R8 skeleton, proven) ----------------
// grid (8, 8, 2): x = cluster rank (32-col slice of h), y = n-group (4 n), z = direction.
// Per step: matvec (W in regs, tied f32x2), butterfly, Gx exchange, gates -> hbuf[p],
// cluster.sync, float4 DSMEM pull of all 8 slices, __syncthreads.
struct __align__(16) GruSmem {
    float Hw[4][4][68];      // [nn][q][64 + 4 pad]  full h for the 4 batch rows
    float hbuf[2][4][32];    // [parity][nn][i]  own 32-col slice of h_new
    float xs[4][512];        // input sequence per batch row
    float Gx[128][4];        // gate exchange: rows {pr,pz,ghn,gin} x [nn]
};

__global__ void __cluster_dims__(8, 1, 1) __launch_bounds__(384, 1)
gru_kernel(const float* __restrict__ inputs,
           const float* __restrict__ w_ih, const float* __restrict__ w_hh,
           const float* __restrict__ b_ih, const float* __restrict__ b_hh)
{
    __shared__ GruSmem sm;

    const int tid = threadIdx.x;
    const int bc  = blockIdx.x;       // cluster rank / column slice
    const int gN  = blockIdx.y;
    const int dd  = blockIdx.z;
    const int rr  = tid >> 2;
    const int q   = tid & 3;
    const int rowG = dd * 768 + ((rr >> 5) << 8) + (bc << 5) + (rr & 31);

    cg::cluster_group cluster = cg::this_cluster();

    // ---- W_hh slice into registers (64 floats = 32 f32x2) ----
    unsigned long long w2[32];
    {
        const ulonglong2* wg = reinterpret_cast<const ulonglong2*>(w_hh + (size_t)rowG * 256 + q * 64);
#pragma unroll
        for (int i = 0; i < 16; ++i) { ulonglong2 t = wg[i]; w2[2 * i] = t.x; w2[2 * i + 1] = t.y; }
    }
    const float wihr = w_ih[rowG];
    const float bihr = b_ih[rowG];
    const float bhhr = b_hh[rowG];

    // inputs: xs[nn][s] = inputs[0][n][s]
    for (int idx = tid; idx < 4 * 512; idx += 384) {
        int nn = idx >> 9, s = idx & 511;
        sm.xs[nn][s] = inputs[(gN * 4 + nn) * D_IN + s];
    }
    // h0 = 0
    for (int idx = tid; idx < 4 * 4 * 68; idx += 384)
        (&sm.Hw[0][0][0])[idx] = 0.f;
    __syncthreads();
    cluster.sync();

    const int bcq = bc >> 1;               // quarter index of own slice within Hw
    const int bco = (bc & 1) * 32;         // float offset within that quarter

    for (int t = 0; t < 512; ++t) {
        const int p = t & 1;
        const int s = dd ? (511 - t) : t;

        // ---- matvec: gh partial over this thread's k-quarter, all 4 batch rows ----
        float part[4];
#pragma unroll
        for (int nn = 0; nn < 4; ++nn) {
            const ulonglong2* hq = reinterpret_cast<const ulonglong2*>(&sm.Hw[nn][q][0]);
            unsigned long long a0 = 0ull, a1 = 0ull;
#pragma unroll
            for (int kk = 0; kk < 16; ++kk) {
                ulonglong2 hv = hq[kk];
                ffma2(a0, w2[2 * kk],     hv.x);
                ffma2(a1, w2[2 * kk + 1], hv.y);
            }
            F2U u0, u1; u0.u = a0; u1.u = a1;
            part[nn] = (u0.f.x + u0.f.y) + (u1.f.x + u1.f.y);
        }

        // ---- butterfly: reduce over q, redistribute nn -> lane q ----
        const int qb = q & 1, qc = q >> 1;
        float keep_lo = qb ? part[1] : part[0];
        float send_lo = qb ? part[0] : part[1];
        float keep_hi = qb ? part[3] : part[2];
        float send_hi = qb ? part[2] : part[3];
        float s0 = keep_lo + __shfl_xor_sync(0xffffffffu, send_lo, 1);
        float s1 = keep_hi + __shfl_xor_sync(0xffffffffu, send_hi, 1);
        float mine = qc ? s1 : s0;
        float othr = qc ? s0 : s1;
        float gh = mine + __shfl_xor_sync(0xffffffffu, othr, 2) + bhhr;  // full gh for nn=q
        float gi = fmaf(sm.xs[q][s], wihr, bihr);

        if (rr < 64) sm.Gx[rr][q] = gh + gi;
        else { sm.Gx[rr][q] = gh; sm.Gx[rr + 32][q] = gi; }
        __syncthreads();

        // ---- gates (warps 0..3 = 4 n x 32 cols), write own slice to hbuf ----
        if (tid < 128) {
            const int n2 = tid >> 5;
            const int i  = tid & 31;
            float pr  = sm.Gx[i][n2];
            float pz  = sm.Gx[32 + i][n2];
            float ghn = sm.Gx[64 + i][n2];
            float gin = sm.Gx[96 + i][n2];
            float r = 1.f / (1.f + __expf(-pr));
            float z = 1.f / (1.f + __expf(-pz));
            float npre = fmaf(r, ghn, gin);
            float tn = 1.f - 2.f / (1.f + __expf(2.f * npre));
            const int colg = (bc << 5) + i;
            float hold = sm.Hw[n2][bcq][bco + i];
            float hnew = fmaf(z, hold - tn, tn);   // (1-z)*tn + z*hold

            const int n = gN * 4 + n2;
            g_M[(size_t)n * M_PER_N + s * 512 + dd * 256 + colg] = hnew;
            sm.hbuf[p][n2][i] = hnew;
            if (t == 511)
                g_Mn[n * 512 + dd * 256 + colg] = hnew;
        }

        if (t < 511) {
            cluster.sync();
            // pull all 8 slices into Hw as float4 (256 loads, one round)
            if (tid < 256) {
                const int src = tid >> 5;
                const int rem = tid & 31;
                const int nn  = rem >> 3;
                const int i4  = rem & 7;
                const float* peer = cluster.map_shared_rank(&sm.hbuf[p][0][0], (unsigned)src);
                float4 v = reinterpret_cast<const float4*>(peer)[nn * 8 + i4];
                *reinterpret_cast<float4*>(&sm.Hw[nn][src >> 1][(src & 1) * 32 + i4 * 4]) = v;
            }
            __syncthreads();
        }
    }
    cluster.sync();   // no CTA exits while a peer may still read its hbuf
}

// ---------------- MLP kernel: grid (NB, 2) — y: 0=actor, 1=critic ----------------
__device__ __forceinline__ void layer4(const float* __restrict__ W, const float* __restrict__ B,
                                       const float* __restrict__ in, float* out, int indim)
{
    const int warp = threadIdx.x >> 5, lane = threadIdx.x & 31;
    const int nk4 = indim >> 2;
    const float4* in4 = reinterpret_cast<const float4*>(in);
    for (int j0 = warp * 32; j0 < warp * 32 + 32; j0 += 4) {
        const float4* w0 = reinterpret_cast<const float4*>(W + (size_t)j0 * indim);
        const float4* w1 = reinterpret_cast<const float4*>(W + (size_t)(j0 + 1) * indim);
        const float4* w2 = reinterpret_cast<const float4*>(W + (size_t)(j0 + 2) * indim);
        const float4* w3 = reinterpret_cast<const float4*>(W + (size_t)(j0 + 3) * indim);
        float a0 = 0.f, a1 = 0.f, a2 = 0.f, a3 = 0.f;
        for (int k = lane; k < nk4; k += 32) {
            float4 x = in4[k];
            float4 v0 = __ldg(w0 + k);
            float4 v1 = __ldg(w1 + k);
            float4 v2 = __ldg(w2 + k);
            float4 v3 = __ldg(w3 + k);
            a0 += v0.x * x.x + v0.y * x.y + v0.z * x.z + v0.w * x.w;
            a1 += v1.x * x.x + v1.y * x.y + v1.z * x.z + v1.w * x.w;
            a2 += v2.x * x.x + v2.y * x.y + v2.z * x.z + v2.w * x.w;
            a3 += v3.x * x.x + v3.y * x.y + v3.z * x.z + v3.w * x.w;
        }
#pragma unroll
        for (int o = 16; o; o >>= 1) {
            a0 += __shfl_down_sync(0xffffffffu, a0, o);
            a1 += __shfl_down_sync(0xffffffffu, a1, o);
            a2 += __shfl_down_sync(0xffffffffu, a2, o);
            a3 += __shfl_down_sync(0xffffffffu, a3, o);
        }
        if (lane == 0) {
            out[j0]     = fmaxf(a0 + B[j0],     0.f);
            out[j0 + 1] = fmaxf(a1 + B[j0 + 1], 0.f);
            out[j0 + 2] = fmaxf(a2 + B[j0 + 2], 0.f);
            out[j0 + 3] = fmaxf(a3 + B[j0 + 3], 0.f);
        }
    }
}

__global__ void __launch_bounds__(256)
mlp_kernel(const float* __restrict__ rnn,
           const float* __restrict__ aw0, const float* __restrict__ ab0,
           const float* __restrict__ aw1, const float* __restrict__ ab1,
           const float* __restrict__ alw, const float* __restrict__ alb,
           const float* __restrict__ cw0, const float* __restrict__ cb0,
           const float* __restrict__ cw1, const float* __restrict__ cb1,
           const float* __restrict__ cow, const float* __restrict__ cob)
{
    __shared__ __align__(16) float hn[1024];
    __shared__ __align__(16) float h1[256];
    __shared__ __align__(16) float h2[256];
    const int n = blockIdx.x, br = blockIdx.y, tid = threadIdx.x;
    const bool newep = (g_nonzero == 0);
    const float* hx = rnn + (size_t)n * TOTAL;
    int P = (int)hx[P_OFF];
    if (P < 0) P = 0; if (P > 511) P = 511;

    const float* w0 = br ? cw0 : aw0;  const float* b0 = br ? cb0 : ab0;
    const float* w1 = br ? cw1 : aw1;  const float* b1 = br ? cb1 : ab1;
    const float* wo = br ? cow : alw;  const float* bo = br ? cob : alb;

    // hn = [ Mn interleaved (h*2 + d), r = M[P][n][:] ]
    for (int k = tid; k < 1024; k += 256) {
        float v;
        if (k < 512) {
            int h = k >> 1, d2 = k & 1;
            v = newep ? g_Mn[n * 512 + d2 * 256 + h] : hx[MN_OFF + d2 * 256 + h];
        } else {
            int kk = k - 512;
            v = newep ? g_M[(size_t)n * M_PER_N + P * 512 + kk] : hx[M_OFF + P * 512 + kk];
        }
        hn[k] = v;
    }
    __syncthreads();

    layer4(w0, b0, hn, h1, 1024);
    __syncthreads();
    layer4(w1, b1, h1, h2, 256);
    __syncthreads();
    if (tid < 32) {
        float acc = 0.f;
        for (int k = tid; k < 256; k += 32) acc = fmaf(wo[k], h2[k], acc);
#pragma unroll
        for (int o = 16; o; o >>= 1) acc += __shfl_down_sync(0xffffffffu, acc, o);
        if (tid == 0) { if (br) g_v[n] = acc + bo[0]; else g_loc[n] = acc + bo[0]; }
    }
}

// ---------------- output: compute slice t=0 once ----------------
__global__ void __launch_bounds__(256)
fill_one_kernel(const float* __restrict__ inputs, const float* __restrict__ rnn,
                const float* __restrict__ eps, const float* __restrict__ logstd,
                float* __restrict__ out)
{
    int o = blockIdx.x * 256 + threadIdx.x;
    if (o >= TOTAL) return;
    const int n = blockIdx.y;
    const float* hx = rnn + (size_t)n * TOTAL;
    const bool newep = (g_nonzero == 0);

    float val;
    if (o >= M_OFF) {
        if (o < MN_OFF) {
            val = newep ? g_M[(size_t)n * M_PER_N + (o - M_OFF)] : hx[o];
        } else {
            val = newep ? g_Mn[n * 512 + (o - MN_OFF)] : hx[o];
        }
    } else if (o >= 4 && o < P_OFF) {
        val = hx[o];                         // hx_h passthrough
    } else if (o == P_OFF) {
        int P = (int)hx[P_OFF];
        val = (float)((P + 1) & 511);        // (P+1) % 512
    } else if (o == 0) {
        float act = inputs[(size_t)n * D_IN + (D_IN - 1)];      // t=0
        float scale = expf(logstd[0]);
        val = (act < 0.f) ? fmaf(scale, eps[n], g_loc[n]) : act;
    } else if (o == 1) {
        val = g_loc[n];
    } else if (o == 2) {
        val = expf(logstd[0]);
    } else { // o == 3
        val = g_v[n];
    }
    out[(size_t)n * TOTAL + o] = val;
}

// ---------------- replicate slice 0 -> slices 1..8 (float4, 1 read 8 writes) ----------------
__global__ void __launch_bounds__(256)
replicate_kernel(float* __restrict__ out)
{
    size_t i = (size_t)blockIdx.x * 256 + threadIdx.x;
    if (i >= SLICE_F4) return;
    const float4 v = reinterpret_cast<const float4*>(out)[i];
    float4* dst = reinterpret_cast<float4*>(out);
#pragma unroll
    for (int t = 1; t < 9; ++t)
        __stcs(dst + (size_t)t * SLICE_F4 + i, v);
}

// ---------------- fixup per-t action values (o == 0) for slices 1..8 ----------------
__global__ void fixup_kernel(const float* __restrict__ inputs, const float* __restrict__ eps,
                             const float* __restrict__ logstd, float* __restrict__ out)
{
    const int idx = threadIdx.x;          // 256 = 8 slices x 32 n
    const int t9 = 1 + (idx >> 5);
    const int n  = idx & 31;
    const int teff = (t9 < 8) ? t9 : 7;
    float act = inputs[(size_t)(teff * NB + n) * D_IN + (D_IN - 1)];
    float scale = expf(logstd[0]);
    float val = (act < 0.f) ? fmaf(scale, eps[teff * NB + n], g_loc[n]) : act;
    out[(size_t)(t9 * NB + n) * TOTAL] = val;
}

// ---------------- launch ----------------
extern "C" void kernel_launch(void* const* d_in, const int* in_sizes, int n_in,
                              void* d_out, int out_size)
{
    const float* inputs = (const float*)d_in[0];
    const float* rnn    = (const float*)d_in[1];
    const float* eps    = (const float*)d_in[2];
    const float* gwih   = (const float*)d_in[3];
    const float* gwhh   = (const float*)d_in[4];
    const float* gbih   = (const float*)d_in[5];
    const float* gbhh   = (const float*)d_in[6];
    const float* aw0    = (const float*)d_in[7];
    const float* ab0    = (const float*)d_in[8];
    const float* aw1    = (const float*)d_in[9];
    const float* ab1    = (const float*)d_in[10];
    const float* alw    = (const float*)d_in[11];
    const float* alb    = (const float*)d_in[12];
    const float* alogstd= (const float*)d_in[13];
    const float* cw0    = (const float*)d_in[14];
    const float* cb0    = (const float*)d_in[15];
    const float* cw1    = (const float*)d_in[16];
    const float* cb1    = (const float*)d_in[17];
    const float* cow    = (const float*)d_in[18];
    const float* cob    = (const float*)d_in[19];
    float* out = (float*)d_out;

    (void)in_sizes; (void)n_in; (void)out_size;

    scan_flag_kernel<<<512, 256>>>(rnn);
    gru_kernel<<<dim3(8, 8, 2), 384>>>(inputs, gwih, gwhh, gbih, gbhh);
    mlp_kernel<<<dim3(NB, 2), 256>>>(rnn, aw0, ab0, aw1, ab1, alw, alb,
                                     cw0, cb0, cw1, cb1, cow, cob);
    fill_one_kernel<<<dim3((TOTAL + 255) / 256, NB), 256>>>(inputs, rnn, eps, alogstd, out);
    replicate_kernel<<<(SLICE_F4 + 255) / 256, 256>>>(out);
    fixup_kernel<<<1, 256>>>(inputs, eps, alogstd, out);
}

// round 12
// speedup vs baseline: 4.8641x; 3.0953x over previous
#include <cuda_runtime.h>
#include <cooperative_groups.h>
#include <math.h>

namespace cg = cooperative_groups;

// Problem constants
#define NB      32          // batch N
#define D_IN    513         // S+1
#define TOTAL   262917      // per-(t,n) output row length
#define P_OFF   260
#define M_OFF   261
#define MN_OFF  262405
#define M_PER_N 262144      // S * ND * H
#define SLICE_F4 2103336    // NB*TOTAL/4 (exact)

// Scratch (device globals — no allocation allowed)
__device__ float g_M [NB * M_PER_N];   // [n][s*512 + d*256 + h]
__device__ float g_Mn[NB * 512];       // [n][d*256 + h]
__device__ float g_loc[NB];
__device__ float g_v  [NB];
__device__ int   g_nonzero = 0;        // sticky: set iff rnn input has any nonzero

// ---------------- f32x2 helper (tied accumulator) ----------------
__device__ __forceinline__ void ffma2(unsigned long long& acc,
                                      unsigned long long a, unsigned long long b) {
    asm("fma.rn.f32x2 %0, %1, %2, %0;" : "+l"(acc) : "l"(a), "l"(b));
}
union F2U { unsigned long long u; float2 f; };

// ---------------- flag kernel (sticky, deterministic across replays) ----------------
__global__ void scan_flag_kernel(const float* __restrict__ rnn) {
    if (g_nonzero != 0) return;
    const int NV4 = (NB * TOTAL) / 4;
    const float4* p = reinterpret_cast<const float4*>(rnn);
    bool nz = false;
    for (int i = blockIdx.x * blockDim.x + threadIdx.x; i < NV4; i += gridDim.x * blockDim.x) {
        float4 v = p[i];
        nz |= (v.x != 0.f) | (v.y != 0.f) | (v.z != 0.f) | (v.w != 0.f);
    }
    if (__syncthreads_or(nz) && threadIdx.x == 0) atomicOr(&g_nonzero, 1);
}

// ---------------- GRU: k-split 4-CTA cluster ----------------
// grid (4, 16, 2): x = cluster rank (owns k/h-cols [64r,64r+64)), y = n-group (2 n),
// z = direction. Thread tid owns global gate rows 2tid, 2tid+1 over its CTA's 64 k,
// with the 128 W floats in REGISTERS. Per step:
//   matvec (local h only) -> partial STS (bucketed by dest rank) -> cluster.sync ->
//   128 gate threads pull 3x3 remote partials + local, gates, in-place h, g_M store ->
//   __syncthreads.
// h never crosses CTAs; only 384 partial floats per CTA pair direction per step do.
struct __align__(16) Gru4Smem {
    float pbuf[2][4][384];   // [parity][dest rank][g*128 + n*64 + b]
    float hloc[2][64];       // [nn][cL]  my 64 h-columns, both batch rows
    float xs[2][512];        // input sequence per batch row
};

__global__ void __cluster_dims__(4, 1, 1) __launch_bounds__(384, 1)
gru_kernel(const float* __restrict__ inputs,
           const float* __restrict__ w_ih, const float* __restrict__ w_hh,
           const float* __restrict__ b_ih, const float* __restrict__ b_hh)
{
    __shared__ Gru4Smem sm;

    const int tid = threadIdx.x;
    const int me  = blockIdx.x;        // cluster rank = k-slice = col-slice
    const int gN  = blockIdx.y;        // n-group (2 n)
    const int dd  = blockIdx.z;        // direction

    cg::cluster_group cluster = cg::this_cluster();

    // row assignment: rows r0=2*tid, r1=r0+1 (global gate rows 0..767)
    const int r0   = 2 * tid;
    const int g    = r0 >> 8;              // gate index 0..2
    const int cb   = r0 & 255;             // global column of row r0
    const int dest = cb >> 6;              // rank that owns this column
    const int b    = cb & 63;              // column within dest's slice (even)

    // ---- W rows (2 x 64 k) into registers: 64 ull = 128 regs ----
    unsigned long long w0[32], w1[32];
    {
        const ulonglong2* s0 = reinterpret_cast<const ulonglong2*>(
            w_hh + (size_t)(dd * 768 + r0) * 256 + me * 64);
        const ulonglong2* s1 = reinterpret_cast<const ulonglong2*>(
            w_hh + (size_t)(dd * 768 + r0 + 1) * 256 + me * 64);
#pragma unroll
        for (int i = 0; i < 16; ++i) {
            ulonglong2 a = s0[i]; w0[2 * i] = a.x; w0[2 * i + 1] = a.y;
            ulonglong2 c = s1[i]; w1[2 * i] = c.x; w1[2 * i + 1] = c.y;
        }
    }

    // gate-thread constants (tid<128): column cL = tid>>1, batch n2 = tid&1
    float wih3[3], bih3[3], bhh3[3];
    const int cL = tid >> 1;
    const int n2 = tid & 1;
    if (tid < 128) {
#pragma unroll
        for (int g2 = 0; g2 < 3; ++g2) {
            int rowB = dd * 768 + g2 * 256 + me * 64 + cL;
            wih3[g2] = w_ih[rowB];
            bih3[g2] = b_ih[rowB];
            bhh3[g2] = b_hh[rowB];
        }
    }

    // inputs: xs[nn][s] = inputs[0][n][s]
    for (int idx = tid; idx < 2 * 512; idx += 384) {
        int nn = idx >> 9, s = idx & 511;
        sm.xs[nn][s] = inputs[(gN * 2 + nn) * D_IN + s];
    }
    // h0 = 0
    if (tid < 128) sm.hloc[tid >> 6][tid & 63] = 0.f;
    __syncthreads();
    cluster.sync();

    // peer base pointers (fixed all steps; parity selects buffer at use site)
    const float* peer1_p0 = cluster.map_shared_rank(&sm.pbuf[0][me][0], (me + 1) & 3);
    const float* peer2_p0 = cluster.map_shared_rank(&sm.pbuf[0][me][0], (me + 2) & 3);
    const float* peer3_p0 = cluster.map_shared_rank(&sm.pbuf[0][me][0], (me + 3) & 3);
    const size_t parstep = 4 * 384;   // floats between parity buffers

    for (int t = 0; t < 512; ++t) {
        const int par = t & 1;
        const int s = dd ? (511 - t) : t;

        // ---- matvec over my 64 k, 2 rows x 2 n, W in regs, h local broadcast ----
        unsigned long long a00 = 0ull, a01 = 0ull, a10 = 0ull, a11 = 0ull;
        const ulonglong2* h0q = reinterpret_cast<const ulonglong2*>(&sm.hloc[0][0]);
        const ulonglong2* h1q = reinterpret_cast<const ulonglong2*>(&sm.hloc[1][0]);
#pragma unroll
        for (int kk = 0; kk < 16; ++kk) {
            ulonglong2 hv0 = h0q[kk];
            ffma2(a00, w0[2 * kk],     hv0.x);
            ffma2(a00, w0[2 * kk + 1], hv0.y);
            ffma2(a10, w1[2 * kk],     hv0.x);
            ffma2(a10, w1[2 * kk + 1], hv0.y);
            ulonglong2 hv1 = h1q[kk];
            ffma2(a01, w0[2 * kk],     hv1.x);
            ffma2(a01, w0[2 * kk + 1], hv1.y);
            ffma2(a11, w1[2 * kk],     hv1.x);
            ffma2(a11, w1[2 * kk + 1], hv1.y);
        }
        F2U u00, u01, u10, u11;
        u00.u = a00; u01.u = a01; u10.u = a10; u11.u = a11;
        float p00 = u00.f.x + u00.f.y;   // row r0, n 0
        float p01 = u01.f.x + u01.f.y;   // row r0, n 1
        float p10 = u10.f.x + u10.f.y;   // row r1, n 0
        float p11 = u11.f.x + u11.f.y;   // row r1, n 1

        // ---- bucket partials by destination rank (b even -> b,b+1 adjacent) ----
        float* pb = &sm.pbuf[par][dest][g * 128];
        *reinterpret_cast<float2*>(&pb[b])      = make_float2(p00, p10);
        *reinterpret_cast<float2*>(&pb[64 + b]) = make_float2(p01, p11);

        cluster.sync();   // partials visible cluster-wide (includes CTA barrier)

        // ---- gates: 128 threads = 64 cols x 2 n ----
        if (tid < 128) {
            const float* q1 = peer1_p0 + (size_t)par * parstep;
            const float* q2 = peer2_p0 + (size_t)par * parstep;
            const float* q3 = peer3_p0 + (size_t)par * parstep;
            const float* ql = &sm.pbuf[par][me][0];
            const int base = n2 * 64 + cL;

            float acc3[3];
#pragma unroll
            for (int g2 = 0; g2 < 3; ++g2) {
                int idx = g2 * 128 + base;
                float l  = ql[idx];
                float v1 = q1[idx];
                float v2 = q2[idx];
                float v3 = q3[idx];
                acc3[g2] = ((l + v1) + (v2 + v3)) + bhh3[g2];
            }
            float xv = sm.xs[n2][s];
            float pr  = acc3[0] + fmaf(xv, wih3[0], bih3[0]);
            float pz  = acc3[1] + fmaf(xv, wih3[1], bih3[1]);
            float ghn = acc3[2];
            float gin = fmaf(xv, wih3[2], bih3[2]);
            float r = 1.f / (1.f + __expf(-pr));
            float z = 1.f / (1.f + __expf(-pz));
            float npre = fmaf(r, ghn, gin);
            float tn = 1.f - 2.f / (1.f + __expf(2.f * npre));
            float hold = sm.hloc[n2][cL];
            float hnew = fmaf(z, hold - tn, tn);   // (1-z)*tn + z*hold
            sm.hloc[n2][cL] = hnew;                // in-place (reads done pre-sync)

            const int n = gN * 2 + n2;
            const int colg = me * 64 + cL;
            g_M[(size_t)n * M_PER_N + s * 512 + dd * 256 + colg] = hnew;
            if (t == 511)
                g_Mn[n * 512 + dd * 256 + colg] = hnew;
        }
        __syncthreads();   // h write visible before next matvec
    }
    cluster.sync();   // no CTA exits while a peer may still read its pbuf
}

// ---------------- MLP kernel: grid (NB, 2) — y: 0=actor, 1=critic ----------------
__device__ __forceinline__ void layer4(const float* __restrict__ W, const float* __restrict__ B,
                                       const float* __restrict__ in, float* out, int indim)
{
    const int warp = threadIdx.x >> 5, lane = threadIdx.x & 31;
    const int nk4 = indim >> 2;
    const float4* in4 = reinterpret_cast<const float4*>(in);
    for (int j0 = warp * 32; j0 < warp * 32 + 32; j0 += 4) {
        const float4* w0 = reinterpret_cast<const float4*>(W + (size_t)j0 * indim);
        const float4* w1 = reinterpret_cast<const float4*>(W + (size_t)(j0 + 1) * indim);
        const float4* w2 = reinterpret_cast<const float4*>(W + (size_t)(j0 + 2) * indim);
        const float4* w3 = reinterpret_cast<const float4*>(W + (size_t)(j0 + 3) * indim);
        float a0 = 0.f, a1 = 0.f, a2 = 0.f, a3 = 0.f;
        for (int k = lane; k < nk4; k += 32) {
            float4 x = in4[k];
            float4 v0 = __ldg(w0 + k);
            float4 v1 = __ldg(w1 + k);
            float4 v2 = __ldg(w2 + k);
            float4 v3 = __ldg(w3 + k);
            a0 += v0.x * x.x + v0.y * x.y + v0.z * x.z + v0.w * x.w;
            a1 += v1.x * x.x + v1.y * x.y + v1.z * x.z + v1.w * x.w;
            a2 += v2.x * x.x + v2.y * x.y + v2.z * x.z + v2.w * x.w;
            a3 += v3.x * x.x + v3.y * x.y + v3.z * x.z + v3.w * x.w;
        }
#pragma unroll
        for (int o = 16; o; o >>= 1) {
            a0 += __shfl_down_sync(0xffffffffu, a0, o);
            a1 += __shfl_down_sync(0xffffffffu, a1, o);
            a2 += __shfl_down_sync(0xffffffffu, a2, o);
            a3 += __shfl_down_sync(0xffffffffu, a3, o);
        }
        if (lane == 0) {
            out[j0]     = fmaxf(a0 + B[j0],     0.f);
            out[j0 + 1] = fmaxf(a1 + B[j0 + 1], 0.f);
            out[j0 + 2] = fmaxf(a2 + B[j0 + 2], 0.f);
            out[j0 + 3] = fmaxf(a3 + B[j0 + 3], 0.f);
        }
    }
}

__global__ void __launch_bounds__(256)
mlp_kernel(const float* __restrict__ rnn,
           const float* __restrict__ aw0, const float* __restrict__ ab0,
           const float* __restrict__ aw1, const float* __restrict__ ab1,
           const float* __restrict__ alw, const float* __restrict__ alb,
           const float* __restrict__ cw0, const float* __restrict__ cb0,
           const float* __restrict__ cw1, const float* __restrict__ cb1,
           const float* __restrict__ cow, const float* __restrict__ cob)
{
    __shared__ __align__(16) float hn[1024];
    __shared__ __align__(16) float h1[256];
    __shared__ __align__(16) float h2[256];
    const int n = blockIdx.x, br = blockIdx.y, tid = threadIdx.x;
    const bool newep = (g_nonzero == 0);
    const float* hx = rnn + (size_t)n * TOTAL;
    int P = (int)hx[P_OFF];
    if (P < 0) P = 0; if (P > 511) P = 511;

    const float* w0 = br ? cw0 : aw0;  const float* b0 = br ? cb0 : ab0;
    const float* w1 = br ? cw1 : aw1;  const float* b1 = br ? cb1 : ab1;
    const float* wo = br ? cow : alw;  const float* bo = br ? cob : alb;

    for (int k = tid; k < 1024; k += 256) {
        float v;
        if (k < 512) {
            int h = k >> 1, d2 = k & 1;
            v = newep ? g_Mn[n * 512 + d2 * 256 + h] : hx[MN_OFF + d2 * 256 + h];
        } else {
            int kk = k - 512;
            v = newep ? g_M[(size_t)n * M_PER_N + P * 512 + kk] : hx[M_OFF + P * 512 + kk];
        }
        hn[k] = v;
    }
    __syncthreads();

    layer4(w0, b0, hn, h1, 1024);
    __syncthreads();
    layer4(w1, b1, h1, h2, 256);
    __syncthreads();
    if (tid < 32) {
        float acc = 0.f;
        for (int k = tid; k < 256; k += 32) acc = fmaf(wo[k], h2[k], acc);
#pragma unroll
        for (int o = 16; o; o >>= 1) acc += __shfl_down_sync(0xffffffffu, acc, o);
        if (tid == 0) { if (br) g_v[n] = acc + bo[0]; else g_loc[n] = acc + bo[0]; }
    }
}

// ---------------- output: compute slice t=0 once ----------------
__global__ void __launch_bounds__(256)
fill_one_kernel(const float* __restrict__ inputs, const float* __restrict__ rnn,
                const float* __restrict__ eps, const float* __restrict__ logstd,
                float* __restrict__ out)
{
    int o = blockIdx.x * 256 + threadIdx.x;
    if (o >= TOTAL) return;
    const int n = blockIdx.y;
    const float* hx = rnn + (size_t)n * TOTAL;
    const bool newep = (g_nonzero == 0);

    float val;
    if (o >= M_OFF) {
        if (o < MN_OFF) {
            val = newep ? g_M[(size_t)n * M_PER_N + (o - M_OFF)] : hx[o];
        } else {
            val = newep ? g_Mn[n * 512 + (o - MN_OFF)] : hx[o];
        }
    } else if (o >= 4 && o < P_OFF) {
        val = hx[o];                         // hx_h passthrough
    } else if (o == P_OFF) {
        int P = (int)hx[P_OFF];
        val = (float)((P + 1) & 511);        // (P+1) % 512
    } else if (o == 0) {
        float act = inputs[(size_t)n * D_IN + (D_IN - 1)];      // t=0
        float scale = expf(logstd[0]);
        val = (act < 0.f) ? fmaf(scale, eps[n], g_loc[n]) : act;
    } else if (o == 1) {
        val = g_loc[n];
    } else if (o == 2) {
        val = expf(logstd[0]);
    } else { // o == 3
        val = g_v[n];
    }
    out[(size_t)n * TOTAL + o] = val;
}

// ---------------- replicate slice 0 -> slices 1..8 ----------------
__global__ void __launch_bounds__(256)
replicate_kernel(float* __restrict__ out)
{
    size_t i = (size_t)blockIdx.x * 256 + threadIdx.x;
    if (i >= SLICE_F4) return;
    const float4 v = reinterpret_cast<const float4*>(out)[i];
    float4* dst = reinterpret_cast<float4*>(out);
#pragma unroll
    for (int t = 1; t < 9; ++t)
        __stcs(dst + (size_t)t * SLICE_F4 + i, v);
}

// ---------------- fixup per-t action values (o == 0) for slices 1..8 ----------------
__global__ void fixup_kernel(const float* __restrict__ inputs, const float* __restrict__ eps,
                             const float* __restrict__ logstd, float* __restrict__ out)
{
    const int idx = threadIdx.x;          // 256 = 8 slices x 32 n
    const int t9 = 1 + (idx >> 5);
    const int n  = idx & 31;
    const int teff = (t9 < 8) ? t9 : 7;
    float act = inputs[(size_t)(teff * NB + n) * D_IN + (D_IN - 1)];
    float scale = expf(logstd[0]);
    float val = (act < 0.f) ? fmaf(scale, eps[teff * NB + n], g_loc[n]) : act;
    out[(size_t)(t9 * NB + n) * TOTAL] = val;
}

// ---------------- launch ----------------
extern "C" void kernel_launch(void* const* d_in, const int* in_sizes, int n_in,
                              void* d_out, int out_size)
{
    const float* inputs = (const float*)d_in[0];
    const float* rnn    = (const float*)d_in[1];
    const float* eps    = (const float*)d_in[2];
    const float* gwih   = (const float*)d_in[3];
    const float* gwhh   = (const float*)d_in[4];
    const float* gbih   = (const float*)d_in[5];
    const float* gbhh   = (const float*)d_in[6];
    const float* aw0    = (const float*)d_in[7];
    const float* ab0    = (const float*)d_in[8];
    const float* aw1    = (const float*)d_in[9];
    const float* ab1    = (const float*)d_in[10];
    const float* alw    = (const float*)d_in[11];
    const float* alb    = (const float*)d_in[12];
    const float* alogstd= (const float*)d_in[13];
    const float* cw0    = (const float*)d_in[14];
    const float* cb0    = (const float*)d_in[15];
    const float* cw1    = (const float*)d_in[16];
    const float* cb1    = (const float*)d_in[17];
    const float* cow    = (const float*)d_in[18];
    const float* cob    = (const float*)d_in[19];
    float* out = (float*)d_out;

    (void)in_sizes; (void)n_in; (void)out_size;

    scan_flag_kernel<<<512, 256>>>(rnn);
    gru_kernel<<<dim3(4, 16, 2), 384>>>(inputs, gwih, gwhh, gbih, gbhh);
    mlp_kernel<<<dim3(NB, 2), 256>>>(rnn, aw0, ab0, aw1, ab1, alw, alb,
                                     cw0, cb0, cw1, cb1, cow, cob);
    fill_one_kernel<<<dim3((TOTAL + 255) / 256, NB), 256>>>(inputs, rnn, eps, alogstd, out);
    replicate_kernel<<<(SLICE_F4 + 255) / 256, 256>>>(out);
    fixup_kernel<<<1, 256>>>(inputs, eps, alogstd, out);
}